// round 9
// baseline (speedup 1.0000x reference)
#include <cuda_runtime.h>
#include <cuda_bf16.h>

// ESN: T=2048 steps, N=2048 reservoir, D=128 input.
// out[t] = erf(U[t] + W_res @ out[t-1]) * 1/sqrt(N),  U = input @ W_in^T
#define T_STEPS 2048
#define N_RES   2048
#define D_IN    128
#define GBLK    128          // persistent blocks (1 per SM, all co-resident)
#define ROWS_PER_BLK 16      // N_RES / GBLK
#define NTHREADS 256
#define CPT      8           // columns per thread = N_RES / NTHREADS
#define NPAIR    8           // row pairs per block (f32x2 packs 2 rows)
#define INV_SQRT_N 0.022097086912079612f

__device__ float    g_U[T_STEPS * N_RES];   // input projection scratch (16 MB)
__device__ unsigned g_scount;               // accumulating step counter (never reset)
__device__ unsigned g_count;                // init-barrier arrive counter
__device__ unsigned g_epoch;                // init-barrier epoch (monotonic across runs)

typedef unsigned long long u64;

__device__ __forceinline__ u64 pack2(float lo, float hi) {
    u64 r; asm("mov.b64 %0, {%1,%2};" : "=l"(r) : "f"(lo), "f"(hi)); return r;
}
__device__ __forceinline__ void unpack2(u64 v, float& lo, float& hi) {
    asm("mov.b64 {%0,%1}, %2;" : "=f"(lo), "=f"(hi) : "l"(v));
}
__device__ __forceinline__ void fma2(u64& acc, u64 a, u64 b) {
    asm("fma.rn.f32x2 %0, %1, %2, %0;" : "+l"(acc) : "l"(a), "l"(b));
}
__device__ __forceinline__ u64 add2(u64 a, u64 b) {
    u64 r; asm("add.rn.f32x2 %0, %1, %2;" : "=l"(r) : "l"(a), "l"(b)); return r;
}
__device__ __forceinline__ u64 shfl_xor64(u64 v, int m) {
    unsigned lo = (unsigned)v, hi = (unsigned)(v >> 32);
    lo = __shfl_xor_sync(0xffffffffu, lo, m);
    hi = __shfl_xor_sync(0xffffffffu, hi, m);
    return ((u64)hi << 32) | (u64)lo;
}

// One-time grid barrier at kernel start (epoch + counter-base agreement).
__device__ __forceinline__ void grid_barrier(int tid, unsigned target) {
    __syncthreads();
    if (tid == 0) {
        unsigned prev;
        asm volatile("atom.release.gpu.global.add.u32 %0, [%1], %2;"
                     : "=r"(prev) : "l"(&g_count), "r"(1u) : "memory");
        if (prev == (unsigned)(GBLK - 1)) {
            asm volatile("st.relaxed.gpu.global.u32 [%0], %1;"
                         :: "l"(&g_count), "r"(0u) : "memory");
            asm volatile("st.release.gpu.global.u32 [%0], %1;"
                         :: "l"(&g_epoch), "r"(target) : "memory");
        } else {
            unsigned cur;
            do {
                asm volatile("ld.acquire.gpu.global.u32 %0, [%1];"
                             : "=r"(cur) : "l"(&g_epoch) : "memory");
            } while (cur != target);
        }
    }
    __syncthreads();
}

// ---------------------------------------------------------------------------
// Kernel 1: U[t][n] = sum_d input[t][d] * W_in[n][d]   (2048 x 2048 x 128)
// ---------------------------------------------------------------------------
__global__ void __launch_bounds__(256) u_gemm_kernel(
    const float* __restrict__ inp, const float* __restrict__ win)
{
    __shared__ float As[32][129];
    __shared__ float Bs[32][129];
    const int tid = threadIdx.x;
    const int t0 = blockIdx.y * 32;
    const int n0 = blockIdx.x * 32;

    #pragma unroll
    for (int i = 0; i < 4; i++) {
        int f   = tid + i * 256;
        int row = f >> 5;
        int c4  = (f & 31) << 2;
        float4 va = *(const float4*)(inp + (t0 + row) * D_IN + c4);
        float4 vb = *(const float4*)(win + (n0 + row) * D_IN + c4);
        As[row][c4] = va.x; As[row][c4 + 1] = va.y; As[row][c4 + 2] = va.z; As[row][c4 + 3] = va.w;
        Bs[row][c4] = vb.x; Bs[row][c4 + 1] = vb.y; Bs[row][c4 + 2] = vb.z; Bs[row][c4 + 3] = vb.w;
    }
    __syncthreads();

    const int tx = tid & 15, ty = tid >> 4;
    float a00 = 0.f, a01 = 0.f, a10 = 0.f, a11 = 0.f;
    #pragma unroll 16
    for (int k = 0; k < D_IN; k++) {
        float x0 = As[2 * ty][k],     x1 = As[2 * ty + 1][k];
        float y0 = Bs[2 * tx][k],     y1 = Bs[2 * tx + 1][k];
        a00 = fmaf(x0, y0, a00); a01 = fmaf(x0, y1, a01);
        a10 = fmaf(x1, y0, a10); a11 = fmaf(x1, y1, a11);
    }
    const int r = t0 + 2 * ty, c = n0 + 2 * tx;
    g_U[r * N_RES + c]           = a00;
    g_U[r * N_RES + c + 1]       = a01;
    g_U[(r + 1) * N_RES + c]     = a10;
    g_U[(r + 1) * N_RES + c + 1] = a11;
}

// ---------------------------------------------------------------------------
// Kernel 2: persistent recurrence, R8 proven core + staggered multi-poller.
//   producer: out stores -> bar.sync -> tid0 red.release.gpu.add(counter)
//   wait:     lane0 of warps 0-3 race-poll counter (phase-drifted sampling,
//             ~RT/5 detect); winner st.release.cta -> smem go word; every
//             warp spins ld.acquire.cta on go (~30cyc granularity, no bar).
// Ordering: STG -> bar -> red.release.gpu -> ld.acquire.gpu -> st.release.cta
//           -> ld.acquire.cta -> ldcg   (transitive happens-before).
// ---------------------------------------------------------------------------
__global__ void __launch_bounds__(NTHREADS, 1) esn_recur_kernel(
    const float* __restrict__ wres, float* __restrict__ out)
{
    __shared__ u64 red[NPAIR * NTHREADS];   // 16 KB reduction staging
    __shared__ unsigned s_cbase;
    __shared__ unsigned s_go;               // monotonic per-launch step flag

    const int tid = threadIdx.x;
    const int bid = blockIdx.x;
    const int r0  = bid * ROWS_PER_BLK;
    const int c0  = tid * CPT;
    const int wp  = tid >> 5, ln = tid & 31;
    const bool poller = (ln == 0) && (wp < 4);

    // Load W_res slice: w[p][c] = {W[r0+2p][c0+c], W[r0+2p+1][c0+c]}
    u64 w[NPAIR][CPT];
    #pragma unroll
    for (int p = 0; p < NPAIR; p++) {
        const float4* ra = (const float4*)(wres + (r0 + 2 * p)     * N_RES + c0);
        const float4* rb = (const float4*)(wres + (r0 + 2 * p + 1) * N_RES + c0);
        float4 a0 = ra[0], a1 = ra[1];
        float4 b0 = rb[0], b1 = rb[1];
        w[p][0] = pack2(a0.x, b0.x); w[p][1] = pack2(a0.y, b0.y);
        w[p][2] = pack2(a0.z, b0.z); w[p][3] = pack2(a0.w, b0.w);
        w[p][4] = pack2(a1.x, b1.x); w[p][5] = pack2(a1.y, b1.y);
        w[p][6] = pack2(a1.z, b1.z); w[p][7] = pack2(a1.w, b1.w);
    }

    // Snapshot the quiescent step-counter + init smem; init barrier ensures
    // all blocks agree before any arrival.
    if (tid == 0) {
        unsigned c;
        asm volatile("ld.relaxed.gpu.global.u32 %0, [%1];" : "=r"(c) : "l"(&g_scount) : "memory");
        s_cbase = c;
        s_go = 0;
    }
    unsigned e0;
    asm volatile("ld.acquire.gpu.global.u32 %0, [%1];" : "=r"(e0) : "l"(&g_epoch) : "memory");
    grid_barrier(tid, e0 + 1);
    const unsigned cbase = s_cbase;

    // Step 0: x0 = erf(U[0]) * inv_sqrt_n ; then arrive.
    if (tid < ROWS_PER_BLK)
        out[r0 + tid] = erff(g_U[r0 + tid]) * INV_SQRT_N;
    __syncthreads();   // out stores happen-before tid0's release-arrival
    if (tid == 0)
        asm volatile("red.release.gpu.global.add.u32 [%0], %1;"
                     :: "l"(&g_scount), "r"(1u) : "memory");

    #pragma unroll 1
    for (int t = 1; t < T_STEPS; t++) {
        // Prefetch U[t] for my row (lanes 0/1 of each warp) before the wait.
        float u = 0.f;
        if (ln < 2) u = __ldg(&g_U[t * N_RES + r0 + 2 * wp + ln]);

        // 4 phase-drifted pollers race on the global counter.
        if (poller) {
            const unsigned tgt = cbase + (unsigned)(GBLK * t);
            for (;;) {
                unsigned cur;
                asm volatile("ld.acquire.gpu.global.u32 %0, [%1];"
                             : "=r"(cur) : "l"(&g_scount) : "memory");
                if ((int)(cur - tgt) >= 0) {
                    asm volatile("st.release.cta.u32 [%0], %1;"
                                 :: "l"(&s_go), "r"((unsigned)t) : "memory");
                    break;
                }
                unsigned g;
                asm volatile("ld.acquire.cta.u32 %0, [%1];"
                             : "=r"(g) : "l"(&s_go) : "memory");
                if ((int)(g - (unsigned)t) >= 0) break;
            }
        }
        // Every warp spins on the smem go word (fine-grained, no bar).
        {
            unsigned g;
            do {
                asm volatile("ld.acquire.cta.u32 %0, [%1];"
                             : "=r"(g) : "l"(&s_go) : "memory");
            } while ((int)(g - (unsigned)t) < 0);
        }

        // Load my 8 x values from the previous out row (L1 bypass: remote SMs).
        const float4* xp = (const float4*)(out + (t - 1) * N_RES + c0);
        float4 xv0 = __ldcg(xp);
        float4 xv1 = __ldcg(xp + 1);
        u64 xx[CPT];
        xx[0] = pack2(xv0.x, xv0.x); xx[1] = pack2(xv0.y, xv0.y);
        xx[2] = pack2(xv0.z, xv0.z); xx[3] = pack2(xv0.w, xv0.w);
        xx[4] = pack2(xv1.x, xv1.x); xx[5] = pack2(xv1.y, xv1.y);
        xx[6] = pack2(xv1.z, xv1.z); xx[7] = pack2(xv1.w, xv1.w);

        u64 acc[NPAIR];
        #pragma unroll
        for (int p = 0; p < NPAIR; p++) acc[p] = 0ULL;
        #pragma unroll
        for (int c = 0; c < CPT; c++) {
            #pragma unroll
            for (int p = 0; p < NPAIR; p++) fma2(acc[p], w[p][c], xx[c]);
        }

        // Stage partials; warp wp reduces row-pair wp across 256 threads.
        #pragma unroll
        for (int p = 0; p < NPAIR; p++) red[p * NTHREADS + tid] = acc[p];
        __syncthreads();

        u64 s = red[wp * NTHREADS + ln];
        #pragma unroll
        for (int k = 1; k < 8; k++) s = add2(s, red[wp * NTHREADS + ln + 32 * k]);
        #pragma unroll
        for (int m = 16; m >= 1; m >>= 1) s = add2(s, shfl_xor64(s, m));
        // Every lane now holds the full {row 2wp, row 2wp+1} dot-product pair.

        // Lanes 0/1 each finish one row: erf + out store (parallel erfs).
        if (ln < 2) {
            float lo, hi; unpack2(s, lo, hi);
            float pre = u + (ln == 0 ? lo : hi);
            out[t * N_RES + r0 + 2 * wp + ln] = erff(pre) * INV_SQRT_N;
        }
        __syncthreads();   // out stores done + red[] safe; HB to tid0 arrival

        if (tid == 0)
            asm volatile("red.release.gpu.global.add.u32 [%0], %1;"
                         :: "l"(&g_scount), "r"(1u) : "memory");
    }
}

// ---------------------------------------------------------------------------
extern "C" void kernel_launch(void* const* d_in, const int* in_sizes, int n_in,
                              void* d_out, int out_size)
{
    const float* input = (const float*)d_in[0];   // (2048, 128)
    const float* w_in  = (const float*)d_in[1];   // (2048, 128)
    const float* w_res = (const float*)d_in[2];   // (2048, 2048)
    float* out = (float*)d_out;                   // (2048, 2048)

    u_gemm_kernel<<<dim3(N_RES / 32, T_STEPS / 32), 256>>>(input, w_in);
    esn_recur_kernel<<<GBLK, NTHREADS>>>(w_res, out);
}

// round 10
// speedup vs baseline: 1.1656x; 1.1656x over previous
#include <cuda_runtime.h>
#include <cuda_bf16.h>

// ESN: T=2048 steps, N=2048 reservoir, D=128 input.
// out[t] = erf(U[t] + W_res @ out[t-1]) * 1/sqrt(N),  U = input @ W_in^T
#define T_STEPS 2048
#define N_RES   2048
#define D_IN    128
#define GBLK    128          // persistent blocks (1 per SM, all co-resident)
#define ROWS_PER_BLK 16      // N_RES / GBLK
#define NTHREADS 256
#define NQUAD   16           // float4 chunks per lane (2048 cols / (32 lanes * 4))
#define INV_SQRT_N 0.022097086912079612f

__device__ float    g_U[T_STEPS * N_RES];   // input projection scratch (16 MB)
__device__ unsigned g_scount;               // accumulating step counter (never reset)
__device__ unsigned g_count;                // init-barrier arrive counter
__device__ unsigned g_epoch;                // init-barrier epoch (monotonic across runs)

typedef unsigned long long u64;

__device__ __forceinline__ u64 pack2(float lo, float hi) {
    u64 r; asm("mov.b64 %0, {%1,%2};" : "=l"(r) : "f"(lo), "f"(hi)); return r;
}
__device__ __forceinline__ void unpack2(u64 v, float& lo, float& hi) {
    asm("mov.b64 {%0,%1}, %2;" : "=f"(lo), "=f"(hi) : "l"(v));
}
__device__ __forceinline__ void fma2(u64& acc, u64 a, u64 b) {
    asm("fma.rn.f32x2 %0, %1, %2, %0;" : "+l"(acc) : "l"(a), "l"(b));
}
__device__ __forceinline__ u64 add2(u64 a, u64 b) {
    u64 r; asm("add.rn.f32x2 %0, %1, %2;" : "=l"(r) : "l"(a), "l"(b)); return r;
}
__device__ __forceinline__ u64 shfl_xor64(u64 v, int m) {
    unsigned lo = (unsigned)v, hi = (unsigned)(v >> 32);
    lo = __shfl_xor_sync(0xffffffffu, lo, m);
    hi = __shfl_xor_sync(0xffffffffu, hi, m);
    return ((u64)hi << 32) | (u64)lo;
}

// One-time grid barrier at kernel start (epoch + counter-base agreement).
__device__ __forceinline__ void grid_barrier(int tid, unsigned target) {
    __syncthreads();
    if (tid == 0) {
        unsigned prev;
        asm volatile("atom.release.gpu.global.add.u32 %0, [%1], %2;"
                     : "=r"(prev) : "l"(&g_count), "r"(1u) : "memory");
        if (prev == (unsigned)(GBLK - 1)) {
            asm volatile("st.relaxed.gpu.global.u32 [%0], %1;"
                         :: "l"(&g_count), "r"(0u) : "memory");
            asm volatile("st.release.gpu.global.u32 [%0], %1;"
                         :: "l"(&g_epoch), "r"(target) : "memory");
        } else {
            unsigned cur;
            do {
                asm volatile("ld.acquire.gpu.global.u32 %0, [%1];"
                             : "=r"(cur) : "l"(&g_epoch) : "memory");
            } while (cur != target);
        }
    }
    __syncthreads();
}

// ---------------------------------------------------------------------------
// Kernel 1: U[t][n] = sum_d input[t][d] * W_in[n][d]   (2048 x 2048 x 128)
// ---------------------------------------------------------------------------
__global__ void __launch_bounds__(256) u_gemm_kernel(
    const float* __restrict__ inp, const float* __restrict__ win)
{
    __shared__ float As[32][129];
    __shared__ float Bs[32][129];
    const int tid = threadIdx.x;
    const int t0 = blockIdx.y * 32;
    const int n0 = blockIdx.x * 32;

    #pragma unroll
    for (int i = 0; i < 4; i++) {
        int f   = tid + i * 256;
        int row = f >> 5;
        int c4  = (f & 31) << 2;
        float4 va = *(const float4*)(inp + (t0 + row) * D_IN + c4);
        float4 vb = *(const float4*)(win + (n0 + row) * D_IN + c4);
        As[row][c4] = va.x; As[row][c4 + 1] = va.y; As[row][c4 + 2] = va.z; As[row][c4 + 3] = va.w;
        Bs[row][c4] = vb.x; Bs[row][c4 + 1] = vb.y; Bs[row][c4 + 2] = vb.z; Bs[row][c4 + 3] = vb.w;
    }
    __syncthreads();

    const int tx = tid & 15, ty = tid >> 4;
    float a00 = 0.f, a01 = 0.f, a10 = 0.f, a11 = 0.f;
    #pragma unroll 16
    for (int k = 0; k < D_IN; k++) {
        float x0 = As[2 * ty][k],     x1 = As[2 * ty + 1][k];
        float y0 = Bs[2 * tx][k],     y1 = Bs[2 * tx + 1][k];
        a00 = fmaf(x0, y0, a00); a01 = fmaf(x0, y1, a01);
        a10 = fmaf(x1, y0, a10); a11 = fmaf(x1, y1, a11);
    }
    const int r = t0 + 2 * ty, c = n0 + 2 * tx;
    g_U[r * N_RES + c]           = a00;
    g_U[r * N_RES + c + 1]       = a01;
    g_U[(r + 1) * N_RES + c]     = a10;
    g_U[(r + 1) * N_RES + c + 1] = a11;
}

// ---------------------------------------------------------------------------
// Kernel 2: persistent recurrence. R8's proven sync (1 poller/block counting
// barrier + bar.sync broadcast) with a warp-per-row-pair data phase:
//   warp wp owns rows {r0+2wp, r0+2wp+1}; lane ln covers cols 4*(ln+32i).
//   Reduction is a single intra-warp butterfly — NO smem staging round.
// x-row loads are L1-cached (all 8 warps read the same 8KB row; first warp
// fills L1, rest hit). Safe: acquire->bar HB chain + per-launch L1 flush +
// first-touch-after-write within the launch.
// ---------------------------------------------------------------------------
__global__ void __launch_bounds__(NTHREADS, 1) esn_recur_kernel(
    const float* __restrict__ wres, float* __restrict__ out)
{
    __shared__ unsigned s_cbase;

    const int tid = threadIdx.x;
    const int bid = blockIdx.x;
    const int r0  = bid * ROWS_PER_BLK;
    const int wp  = tid >> 5, ln = tid & 31;

    // W slice for warp wp's row pair: w[i][j] = {W[r0+2wp][c], W[r0+2wp+1][c]},
    // c = 4*(ln + 32*i) + j. 64 u64 registers.
    u64 w[NQUAD][4];
    {
        const float4* ra = (const float4*)(wres + (r0 + 2 * wp)     * N_RES) + ln;
        const float4* rb = (const float4*)(wres + (r0 + 2 * wp + 1) * N_RES) + ln;
        #pragma unroll
        for (int i = 0; i < NQUAD; i++) {
            float4 a = ra[32 * i];
            float4 b = rb[32 * i];
            w[i][0] = pack2(a.x, b.x); w[i][1] = pack2(a.y, b.y);
            w[i][2] = pack2(a.z, b.z); w[i][3] = pack2(a.w, b.w);
        }
    }

    // Snapshot quiescent step-counter; init barrier ensures agreement before
    // any arrival.
    if (tid == 0) {
        unsigned c;
        asm volatile("ld.relaxed.gpu.global.u32 %0, [%1];" : "=r"(c) : "l"(&g_scount) : "memory");
        s_cbase = c;
    }
    unsigned e0;
    asm volatile("ld.acquire.gpu.global.u32 %0, [%1];" : "=r"(e0) : "l"(&g_epoch) : "memory");
    grid_barrier(tid, e0 + 1);
    const unsigned cbase = s_cbase;

    // Step 0: x0 = erf(U[0]) * inv_sqrt_n ; then arrive.
    if (tid < ROWS_PER_BLK)
        out[r0 + tid] = erff(g_U[r0 + tid]) * INV_SQRT_N;
    __syncthreads();   // out stores happen-before tid0's release-arrival
    if (tid == 0)
        asm volatile("red.release.gpu.global.add.u32 [%0], %1;"
                     :: "l"(&g_scount), "r"(1u) : "memory");

    #pragma unroll 1
    for (int t = 1; t < T_STEPS; t++) {
        // Prefetch U[t] for my row (lanes 0/1 of each warp) before the wait.
        float u = 0.f;
        if (ln < 2) u = __ldg(&g_U[t * N_RES + r0 + 2 * wp + ln]);

        // Single-hop barrier wait (proven R8): tid0 polls, bar broadcasts.
        if (tid == 0) {
            const unsigned tgt = cbase + (unsigned)(GBLK * t);
            unsigned cur;
            do {
                asm volatile("ld.acquire.gpu.global.u32 %0, [%1];"
                             : "=r"(cur) : "l"(&g_scount) : "memory");
            } while ((int)(cur - tgt) < 0);
        }
        __syncthreads();   // acquire happens-before all lanes' loads

        // Load the full x row (L1-cached; warp-shared). 16 coalesced LDG.128.
        const float4* xrow = (const float4*)(out + (t - 1) * N_RES) + ln;
        float4 xv[NQUAD];
        #pragma unroll
        for (int i = 0; i < NQUAD; i++) xv[i] = xrow[32 * i];

        // 64 fma2: acc = {dot(row even), dot(row odd)} partial on this lane.
        u64 acc = 0ULL;
        #pragma unroll
        for (int i = 0; i < NQUAD; i++) {
            fma2(acc, w[i][0], pack2(xv[i].x, xv[i].x));
            fma2(acc, w[i][1], pack2(xv[i].y, xv[i].y));
            fma2(acc, w[i][2], pack2(xv[i].z, xv[i].z));
            fma2(acc, w[i][3], pack2(xv[i].w, xv[i].w));
        }

        // Pure intra-warp butterfly (no smem, no extra bar).
        #pragma unroll
        for (int m = 16; m >= 1; m >>= 1) acc = add2(acc, shfl_xor64(acc, m));
        // Every lane now holds {row 2wp, row 2wp+1} full dot products.

        // Lanes 0/1 each finish one row: erf + out store (parallel erfs).
        if (ln < 2) {
            float lo, hi; unpack2(acc, lo, hi);
            float pre = u + (ln == 0 ? lo : hi);
            out[t * N_RES + r0 + 2 * wp + ln] = erff(pre) * INV_SQRT_N;
        }
        __syncthreads();   // all 8 warps' stores happen-before the arrival

        if (tid == 0)
            asm volatile("red.release.gpu.global.add.u32 [%0], %1;"
                         :: "l"(&g_scount), "r"(1u) : "memory");
    }
}

// ---------------------------------------------------------------------------
extern "C" void kernel_launch(void* const* d_in, const int* in_sizes, int n_in,
                              void* d_out, int out_size)
{
    const float* input = (const float*)d_in[0];   // (2048, 128)
    const float* w_in  = (const float*)d_in[1];   // (2048, 128)
    const float* w_res = (const float*)d_in[2];   // (2048, 2048)
    float* out = (float*)d_out;                   // (2048, 2048)

    u_gemm_kernel<<<dim3(N_RES / 32, T_STEPS / 32), 256>>>(input, w_in);
    esn_recur_kernel<<<GBLK, NTHREADS>>>(w_res, out);
}

// round 11
// speedup vs baseline: 1.1890x; 1.0200x over previous
#include <cuda_runtime.h>
#include <cuda_bf16.h>

// ESN: T=2048 steps, N=2048 reservoir, D=128 input.
// out[t] = erf(U[t] + W_res @ out[t-1]) * 1/sqrt(N),  U = input @ W_in^T
#define T_STEPS 2048
#define N_RES   2048
#define D_IN    128
#define GBLK    128          // persistent blocks (1 per SM, all co-resident)
#define ROWS_PER_BLK 16      // N_RES / GBLK
#define NTHREADS 256
#define CPT      8           // columns per thread = N_RES / NTHREADS
#define NPAIR    8           // row pairs per block (f32x2 packs 2 rows)
#define NCELL    4           // split-counter cells (separate L2 lines)
#define CELLSTR  64          // unsigned stride between cells (256B)
#define INV_SQRT_N 0.022097086912079612f

__device__ float    g_U[T_STEPS * N_RES];     // input projection scratch (16 MB)
__device__ unsigned g_scount4[NCELL * CELLSTR]; // split step counters (never reset)
__device__ unsigned g_count;                  // init-barrier arrive counter
__device__ unsigned g_epoch;                  // init-barrier epoch (monotonic)

typedef unsigned long long u64;

__device__ __forceinline__ u64 pack2(float lo, float hi) {
    u64 r; asm("mov.b64 %0, {%1,%2};" : "=l"(r) : "f"(lo), "f"(hi)); return r;
}
__device__ __forceinline__ void unpack2(u64 v, float& lo, float& hi) {
    asm("mov.b64 {%0,%1}, %2;" : "=f"(lo), "=f"(hi) : "l"(v));
}
__device__ __forceinline__ void fma2(u64& acc, u64 a, u64 b) {
    asm("fma.rn.f32x2 %0, %1, %2, %0;" : "+l"(acc) : "l"(a), "l"(b));
}
__device__ __forceinline__ u64 add2(u64 a, u64 b) {
    u64 r; asm("add.rn.f32x2 %0, %1, %2;" : "=l"(r) : "l"(a), "l"(b)); return r;
}
__device__ __forceinline__ u64 shfl_xor64(u64 v, int m) {
    unsigned lo = (unsigned)v, hi = (unsigned)(v >> 32);
    lo = __shfl_xor_sync(0xffffffffu, lo, m);
    hi = __shfl_xor_sync(0xffffffffu, hi, m);
    return ((u64)hi << 32) | (u64)lo;
}

// One-time grid barrier at kernel start (epoch + counter-base agreement).
__device__ __forceinline__ void grid_barrier(int tid, unsigned target) {
    __syncthreads();
    if (tid == 0) {
        unsigned prev;
        asm volatile("atom.release.gpu.global.add.u32 %0, [%1], %2;"
                     : "=r"(prev) : "l"(&g_count), "r"(1u) : "memory");
        if (prev == (unsigned)(GBLK - 1)) {
            asm volatile("st.relaxed.gpu.global.u32 [%0], %1;"
                         :: "l"(&g_count), "r"(0u) : "memory");
            asm volatile("st.release.gpu.global.u32 [%0], %1;"
                         :: "l"(&g_epoch), "r"(target) : "memory");
        } else {
            unsigned cur;
            do {
                asm volatile("ld.acquire.gpu.global.u32 %0, [%1];"
                             : "=r"(cur) : "l"(&g_epoch) : "memory");
            } while (cur != target);
        }
    }
    __syncthreads();
}

// ---------------------------------------------------------------------------
// Kernel 1: U[t][n] = sum_d input[t][d] * W_in[n][d]   (2048 x 2048 x 128)
// ---------------------------------------------------------------------------
__global__ void __launch_bounds__(256) u_gemm_kernel(
    const float* __restrict__ inp, const float* __restrict__ win)
{
    __shared__ float As[32][129];
    __shared__ float Bs[32][129];
    const int tid = threadIdx.x;
    const int t0 = blockIdx.y * 32;
    const int n0 = blockIdx.x * 32;

    #pragma unroll
    for (int i = 0; i < 4; i++) {
        int f   = tid + i * 256;
        int row = f >> 5;
        int c4  = (f & 31) << 2;
        float4 va = *(const float4*)(inp + (t0 + row) * D_IN + c4);
        float4 vb = *(const float4*)(win + (n0 + row) * D_IN + c4);
        As[row][c4] = va.x; As[row][c4 + 1] = va.y; As[row][c4 + 2] = va.z; As[row][c4 + 3] = va.w;
        Bs[row][c4] = vb.x; Bs[row][c4 + 1] = vb.y; Bs[row][c4 + 2] = vb.z; Bs[row][c4 + 3] = vb.w;
    }
    __syncthreads();

    const int tx = tid & 15, ty = tid >> 4;
    float a00 = 0.f, a01 = 0.f, a10 = 0.f, a11 = 0.f;
    #pragma unroll 16
    for (int k = 0; k < D_IN; k++) {
        float x0 = As[2 * ty][k],     x1 = As[2 * ty + 1][k];
        float y0 = Bs[2 * tx][k],     y1 = Bs[2 * tx + 1][k];
        a00 = fmaf(x0, y0, a00); a01 = fmaf(x0, y1, a01);
        a10 = fmaf(x1, y0, a10); a11 = fmaf(x1, y1, a11);
    }
    const int r = t0 + 2 * ty, c = n0 + 2 * tx;
    g_U[r * N_RES + c]           = a00;
    g_U[r * N_RES + c + 1]       = a01;
    g_U[(r + 1) * N_RES + c]     = a10;
    g_U[(r + 1) * N_RES + c + 1] = a11;
}

// ---------------------------------------------------------------------------
// Kernel 2: persistent recurrence == R8's proven core, with the single
// counter replaced by a 4-way split counter:
//   arrival:  tid0 red.release.gpu.add -> cell[bid & 3]   (32 arrivals/cell,
//             ~4x less LTS atomic serialization tail)
//   wait:     lanes 0-3 of warp 0 poll the 4 cells in parallel (one warp
//             instruction = 4 concurrent loads; no extra spinning warps),
//             then bar.sync broadcasts.
// Ordering: per-cell red.release -> same-cell ld.acquire -> bar.sync -> loads.
// ---------------------------------------------------------------------------
__global__ void __launch_bounds__(NTHREADS, 1) esn_recur_kernel(
    const float* __restrict__ wres, float* __restrict__ out)
{
    __shared__ u64 red[NPAIR * NTHREADS];   // 16 KB reduction staging
    __shared__ unsigned s_cbase[NCELL];

    const int tid = threadIdx.x;
    const int bid = blockIdx.x;
    const int r0  = bid * ROWS_PER_BLK;
    const int c0  = tid * CPT;
    const int wp  = tid >> 5, ln = tid & 31;
    unsigned* const mycell = &g_scount4[(bid & (NCELL - 1)) * CELLSTR];

    // Load W_res slice: w[p][c] = {W[r0+2p][c0+c], W[r0+2p+1][c0+c]}
    u64 w[NPAIR][CPT];
    #pragma unroll
    for (int p = 0; p < NPAIR; p++) {
        const float4* ra = (const float4*)(wres + (r0 + 2 * p)     * N_RES + c0);
        const float4* rb = (const float4*)(wres + (r0 + 2 * p + 1) * N_RES + c0);
        float4 a0 = ra[0], a1 = ra[1];
        float4 b0 = rb[0], b1 = rb[1];
        w[p][0] = pack2(a0.x, b0.x); w[p][1] = pack2(a0.y, b0.y);
        w[p][2] = pack2(a0.z, b0.z); w[p][3] = pack2(a0.w, b0.w);
        w[p][4] = pack2(a1.x, b1.x); w[p][5] = pack2(a1.y, b1.y);
        w[p][6] = pack2(a1.z, b1.z); w[p][7] = pack2(a1.w, b1.w);
    }

    // Snapshot quiescent split counters; init barrier ensures agreement
    // before any arrival.
    if (tid < NCELL) {
        unsigned c;
        asm volatile("ld.relaxed.gpu.global.u32 %0, [%1];"
                     : "=r"(c) : "l"(&g_scount4[tid * CELLSTR]) : "memory");
        s_cbase[tid] = c;
    }
    unsigned e0;
    asm volatile("ld.acquire.gpu.global.u32 %0, [%1];" : "=r"(e0) : "l"(&g_epoch) : "memory");
    grid_barrier(tid, e0 + 1);
    const unsigned cb = (tid < NCELL) ? s_cbase[tid] : 0u;

    // Step 0: x0 = erf(U[0]) * inv_sqrt_n ; then arrive at my cell.
    if (tid < ROWS_PER_BLK)
        out[r0 + tid] = erff(g_U[r0 + tid]) * INV_SQRT_N;
    __syncthreads();   // out stores happen-before tid0's release-arrival
    if (tid == 0)
        asm volatile("red.release.gpu.global.add.u32 [%0], %1;"
                     :: "l"(mycell), "r"(1u) : "memory");

    #pragma unroll 1
    for (int t = 1; t < T_STEPS; t++) {
        // Prefetch U[t] for my row (lanes 0/1 of each warp) before the wait.
        float u = 0.f;
        if (ln < 2) u = __ldg(&g_U[t * N_RES + r0 + 2 * wp + ln]);

        // Parallel 4-cell barrier wait: lane c of warp 0 polls cell c until
        // it reaches cbase_c + 32*t (each cell gets 32 arrivals per step).
        if (tid < NCELL) {
            const unsigned tgt = cb + (unsigned)((GBLK / NCELL) * t);
            const unsigned* cell = &g_scount4[tid * CELLSTR];
            unsigned cur;
            do {
                asm volatile("ld.acquire.gpu.global.u32 %0, [%1];"
                             : "=r"(cur) : "l"(cell) : "memory");
            } while ((int)(cur - tgt) < 0);
        }
        __syncthreads();   // all 4 acquires happen-before all lanes' loads

        // Load my 8 x values from the previous out row (L1 bypass: remote SMs).
        const float4* xp = (const float4*)(out + (t - 1) * N_RES + c0);
        float4 xv0 = __ldcg(xp);
        float4 xv1 = __ldcg(xp + 1);
        u64 xx[CPT];
        xx[0] = pack2(xv0.x, xv0.x); xx[1] = pack2(xv0.y, xv0.y);
        xx[2] = pack2(xv0.z, xv0.z); xx[3] = pack2(xv0.w, xv0.w);
        xx[4] = pack2(xv1.x, xv1.x); xx[5] = pack2(xv1.y, xv1.y);
        xx[6] = pack2(xv1.z, xv1.z); xx[7] = pack2(xv1.w, xv1.w);

        u64 acc[NPAIR];
        #pragma unroll
        for (int p = 0; p < NPAIR; p++) acc[p] = 0ULL;
        #pragma unroll
        for (int c = 0; c < CPT; c++) {
            #pragma unroll
            for (int p = 0; p < NPAIR; p++) fma2(acc[p], w[p][c], xx[c]);
        }

        // Stage partials; warp wp reduces row-pair wp across 256 threads.
        #pragma unroll
        for (int p = 0; p < NPAIR; p++) red[p * NTHREADS + tid] = acc[p];
        __syncthreads();

        u64 s = red[wp * NTHREADS + ln];
        #pragma unroll
        for (int k = 1; k < 8; k++) s = add2(s, red[wp * NTHREADS + ln + 32 * k]);
        #pragma unroll
        for (int m = 16; m >= 1; m >>= 1) s = add2(s, shfl_xor64(s, m));
        // Every lane now holds the full {row 2wp, row 2wp+1} dot-product pair.

        // Lanes 0/1 each finish one row: erf + out store (parallel erfs).
        if (ln < 2) {
            float lo, hi; unpack2(s, lo, hi);
            float pre = u + (ln == 0 ? lo : hi);
            out[t * N_RES + r0 + 2 * wp + ln] = erff(pre) * INV_SQRT_N;
        }
        __syncthreads();   // out stores done + red[] safe; HB to tid0 arrival

        if (tid == 0)
            asm volatile("red.release.gpu.global.add.u32 [%0], %1;"
                         :: "l"(mycell), "r"(1u) : "memory");
    }
}

// ---------------------------------------------------------------------------
extern "C" void kernel_launch(void* const* d_in, const int* in_sizes, int n_in,
                              void* d_out, int out_size)
{
    const float* input = (const float*)d_in[0];   // (2048, 128)
    const float* w_in  = (const float*)d_in[1];   // (2048, 128)
    const float* w_res = (const float*)d_in[2];   // (2048, 2048)
    float* out = (float*)d_out;                   // (2048, 2048)

    u_gemm_kernel<<<dim3(N_RES / 32, T_STEPS / 32), 256>>>(input, w_in);
    esn_recur_kernel<<<GBLK, NTHREADS>>>(w_res, out);
}